// round 1
// baseline (speedup 1.0000x reference)
#include <cuda_runtime.h>

#define S_GRID 7
#define N_CH 30
#define L_COORD 5.0f
#define L_NOOBJ 0.5f

// global accumulators: [0]=xy+wh, [1]=obj, [2]=noobj, [3]=class
__device__ float g_sums[4];

__global__ void zero_sums_kernel() {
    if (threadIdx.x < 4) g_sums[threadIdx.x] = 0.0f;
}

__global__ __launch_bounds__(256) void yolo_loss_kernel(
    const float* __restrict__ pred,
    const float* __restrict__ tgt,
    int ncells)
{
    int i = blockIdx.x * blockDim.x + threadIdx.x;

    float s_xywh = 0.0f, s_obj = 0.0f, s_noobj = 0.0f, s_cls = 0.0f;

    if (i < ncells) {
        const float2* p2 = reinterpret_cast<const float2*>(pred + (size_t)i * N_CH);
        const float2* t2 = reinterpret_cast<const float2*>(tgt  + (size_t)i * N_CH);

        float p[N_CH], t[N_CH];
#pragma unroll
        for (int k = 0; k < 15; k++) {
            float2 v = __ldg(p2 + k);
            p[2 * k] = v.x; p[2 * k + 1] = v.y;
        }
#pragma unroll
        for (int k = 0; k < 15; k++) {
            float2 v = __ldg(t2 + k);
            t[2 * k] = v.x; t[2 * k + 1] = v.y;
        }

        float conf_t = t[4];
        float coord = (conf_t > 0.0f) ? 1.0f : 0.0f;
        float noobj = (conf_t == 0.0f) ? 1.0f : 0.0f;

        // target box xyxy (mirror reference op order)
        float inv = 1.0f / (float)S_GRID;  // reference does xy / 7 (fp32 div)
        float tax = t[0] / (float)S_GRID;
        float tay = t[1] / (float)S_GRID;
        float thw = 0.5f * t[2];
        float thh = 0.5f * t[3];
        float tx1 = tax - thw, ty1 = tay - thh;
        float tx2 = tax + thw, ty2 = tay + thh;
        float area_t = (tx2 - tx1) * (ty2 - ty1);
        (void)inv;

        // per-box IoU
        float iou[2];
#pragma unroll
        for (int b = 0; b < 2; b++) {
            const float* pb = p + 5 * b;
            float pax = pb[0] / (float)S_GRID;
            float pay = pb[1] / (float)S_GRID;
            float phw = 0.5f * pb[2];
            float phh = 0.5f * pb[3];
            float px1 = pax - phw, py1 = pay - phh;
            float px2 = pax + phw, py2 = pay + phh;

            float ltx = fmaxf(px1, tx1);
            float lty = fmaxf(py1, ty1);
            float rbx = fminf(px2, tx2);
            float rby = fminf(py2, ty2);
            float w = fmaxf(rbx - ltx, 0.0f);
            float h = fmaxf(rby - lty, 0.0f);
            float inter = w * h;
            float area_p = (px2 - px1) * (py2 - py1);
            iou[b] = inter / (area_p + area_t - inter);
        }

        // argmax, first occurrence on ties: pick 1 only if strictly greater
        int best = (iou[1] > iou[0]) ? 1 : 0;
        float max_iou = fmaxf(iou[0], iou[1]);
        const float* resp = p + 5 * best;

        float dx = resp[0] - t[0];
        float dy = resp[1] - t[1];
        float loss_xy = dx * dx + dy * dy;

        float dw = sqrtf(resp[2]) - sqrtf(t[2]);
        float dh = sqrtf(resp[3]) - sqrtf(t[3]);
        float loss_wh = dw * dw + dh * dh;

        float dob = resp[4] - max_iou;
        float loss_obj = dob * dob;

        float loss_cls = 0.0f;
#pragma unroll
        for (int c = 10; c < 30; c++) {
            float d = p[c] - t[c];
            loss_cls += d * d;
        }

        float d4 = p[4] - t[4];
        float d9 = p[9] - t[9];
        float loss_no = d4 * d4 + d9 * d9;

        s_xywh  = coord * (loss_xy + loss_wh);
        s_obj   = coord * loss_obj;
        s_noobj = noobj * loss_no;
        s_cls   = coord * loss_cls;
    }

    // warp reduction
#pragma unroll
    for (int off = 16; off > 0; off >>= 1) {
        s_xywh  += __shfl_down_sync(0xFFFFFFFFu, s_xywh,  off);
        s_obj   += __shfl_down_sync(0xFFFFFFFFu, s_obj,   off);
        s_noobj += __shfl_down_sync(0xFFFFFFFFu, s_noobj, off);
        s_cls   += __shfl_down_sync(0xFFFFFFFFu, s_cls,   off);
    }

    __shared__ float red[4][8];  // 8 warps per 256-thread block
    int wid = threadIdx.x >> 5;
    int lid = threadIdx.x & 31;
    if (lid == 0) {
        red[0][wid] = s_xywh;
        red[1][wid] = s_obj;
        red[2][wid] = s_noobj;
        red[3][wid] = s_cls;
    }
    __syncthreads();

    if (wid == 0) {
        int nw = (blockDim.x + 31) >> 5;
        float v0 = (lid < nw) ? red[0][lid] : 0.0f;
        float v1 = (lid < nw) ? red[1][lid] : 0.0f;
        float v2 = (lid < nw) ? red[2][lid] : 0.0f;
        float v3 = (lid < nw) ? red[3][lid] : 0.0f;
#pragma unroll
        for (int off = 4; off > 0; off >>= 1) {
            v0 += __shfl_down_sync(0xFFFFFFFFu, v0, off);
            v1 += __shfl_down_sync(0xFFFFFFFFu, v1, off);
            v2 += __shfl_down_sync(0xFFFFFFFFu, v2, off);
            v3 += __shfl_down_sync(0xFFFFFFFFu, v3, off);
        }
        if (lid == 0) {
            atomicAdd(&g_sums[0], v0);
            atomicAdd(&g_sums[1], v1);
            atomicAdd(&g_sums[2], v2);
            atomicAdd(&g_sums[3], v3);
        }
    }
}

__global__ void finalize_kernel(float* __restrict__ out, float inv_bs) {
    float xywh  = g_sums[0];
    float obj   = g_sums[1];
    float noobj = g_sums[2];
    float cls   = g_sums[3];
    out[0] = (L_COORD * xywh + obj + L_NOOBJ * noobj + cls) * inv_bs;
    out[1] = xywh;
    out[2] = obj;
    out[3] = noobj;
    out[4] = cls;
}

extern "C" void kernel_launch(void* const* d_in, const int* in_sizes, int n_in,
                              void* d_out, int out_size) {
    const float* pred = (const float*)d_in[0];
    const float* tgt  = (const float*)d_in[1];
    int ncells = in_sizes[0] / N_CH;            // 8192*7*7 = 401408
    int bs = ncells / (S_GRID * S_GRID);        // 8192

    zero_sums_kernel<<<1, 32>>>();
    int threads = 256;
    int blocks = (ncells + threads - 1) / threads;
    yolo_loss_kernel<<<blocks, threads>>>(pred, tgt, ncells);
    finalize_kernel<<<1, 1>>>((float*)d_out, 1.0f / (float)bs);
}

// round 2
// speedup vs baseline: 1.0667x; 1.0667x over previous
#include <cuda_runtime.h>

#define S_GRID 7
#define N_CH 30
#define L_COORD 5.0f
#define L_NOOBJ 0.5f

#define TPB 128                    // threads per block = cells per block
#define FPB (TPB * N_CH)           // 3840 floats staged per tensor
#define V4PB (FPB / 4)             // 960 float4 per tensor

__device__ float g_sums[4];        // [0]=xy+wh [1]=obj [2]=noobj [3]=class
__device__ unsigned int g_count;

__global__ __launch_bounds__(TPB) void yolo_loss_kernel(
    const float4* __restrict__ pred4,
    const float4* __restrict__ tgt4,
    float* __restrict__ out,
    int ncells, float inv_bs, int nblocks, int total_v4)
{
    __shared__ float sp[FPB];
    __shared__ float st[FPB];
    __shared__ float red[4][4];        // 4 warps
    __shared__ int   s_is_last;

    const int tid = threadIdx.x;
    const int cell = blockIdx.x * TPB + tid;
    const int v4base = blockIdx.x * V4PB;

    // ---- coalesced staging: global float4 -> smem ----
    float4* sp4 = reinterpret_cast<float4*>(sp);
    float4* st4 = reinterpret_cast<float4*>(st);
#pragma unroll
    for (int k = 0; k < (V4PB + TPB - 1) / TPB; k++) {
        int idx = tid + k * TPB;
        if (idx < V4PB) {
            int g = v4base + idx;
            if (g < total_v4) {
                sp4[idx] = __ldg(pred4 + g);
                st4[idx] = __ldg(tgt4  + g);
            } else {
                sp4[idx] = make_float4(0.f, 0.f, 0.f, 0.f);
                st4[idx] = make_float4(0.f, 0.f, 0.f, 0.f);
            }
        }
    }
    __syncthreads();

    float s_xywh = 0.0f, s_obj = 0.0f, s_noobj = 0.0f, s_cls = 0.0f;

    if (cell < ncells) {
        const float* p = sp + tid * N_CH;
        const float* t = st + tid * N_CH;

        float conf_t = t[4];
        float coord = (conf_t > 0.0f) ? 1.0f : 0.0f;
        float noobj = (conf_t == 0.0f) ? 1.0f : 0.0f;

        // target box xyxy (mirror reference op order)
        float tax = t[0] / (float)S_GRID;
        float tay = t[1] / (float)S_GRID;
        float thw = 0.5f * t[2];
        float thh = 0.5f * t[3];
        float tx1 = tax - thw, ty1 = tay - thh;
        float tx2 = tax + thw, ty2 = tay + thh;
        float area_t = (tx2 - tx1) * (ty2 - ty1);

        float iou[2];
#pragma unroll
        for (int b = 0; b < 2; b++) {
            const float* pb = p + 5 * b;
            float pax = pb[0] / (float)S_GRID;
            float pay = pb[1] / (float)S_GRID;
            float phw = 0.5f * pb[2];
            float phh = 0.5f * pb[3];
            float px1 = pax - phw, py1 = pay - phh;
            float px2 = pax + phw, py2 = pay + phh;

            float ltx = fmaxf(px1, tx1);
            float lty = fmaxf(py1, ty1);
            float rbx = fminf(px2, tx2);
            float rby = fminf(py2, ty2);
            float w = fmaxf(rbx - ltx, 0.0f);
            float h = fmaxf(rby - lty, 0.0f);
            float inter = w * h;
            float area_p = (px2 - px1) * (py2 - py1);
            iou[b] = inter / (area_p + area_t - inter);
        }

        // argmax first-occurrence tie-break: pick box1 only if strictly greater
        int best = (iou[1] > iou[0]) ? 1 : 0;
        float max_iou = fmaxf(iou[0], iou[1]);
        const float* resp = p + 5 * best;

        float dx = resp[0] - t[0];
        float dy = resp[1] - t[1];
        float loss_xy = dx * dx + dy * dy;

        float dw = sqrtf(resp[2]) - sqrtf(t[2]);
        float dh = sqrtf(resp[3]) - sqrtf(t[3]);
        float loss_wh = dw * dw + dh * dh;

        float dob = resp[4] - max_iou;
        float loss_obj = dob * dob;

        float loss_cls = 0.0f;
#pragma unroll
        for (int c = 10; c < 30; c++) {
            float d = p[c] - t[c];
            loss_cls += d * d;
        }

        float d4 = p[4] - t[4];
        float d9 = p[9] - t[9];
        float loss_no = d4 * d4 + d9 * d9;

        s_xywh  = coord * (loss_xy + loss_wh);
        s_obj   = coord * loss_obj;
        s_noobj = noobj * loss_no;
        s_cls   = coord * loss_cls;
    }

    // ---- warp reduction ----
#pragma unroll
    for (int off = 16; off > 0; off >>= 1) {
        s_xywh  += __shfl_down_sync(0xFFFFFFFFu, s_xywh,  off);
        s_obj   += __shfl_down_sync(0xFFFFFFFFu, s_obj,   off);
        s_noobj += __shfl_down_sync(0xFFFFFFFFu, s_noobj, off);
        s_cls   += __shfl_down_sync(0xFFFFFFFFu, s_cls,   off);
    }

    int wid = tid >> 5;
    int lid = tid & 31;
    if (lid == 0) {
        red[0][wid] = s_xywh;
        red[1][wid] = s_obj;
        red[2][wid] = s_noobj;
        red[3][wid] = s_cls;
    }
    __syncthreads();

    // ---- block total + global accumulate + last-block finalize ----
    if (tid == 0) {
        float v0 = red[0][0] + red[0][1] + red[0][2] + red[0][3];
        float v1 = red[1][0] + red[1][1] + red[1][2] + red[1][3];
        float v2 = red[2][0] + red[2][1] + red[2][2] + red[2][3];
        float v3 = red[3][0] + red[3][1] + red[3][2] + red[3][3];
        atomicAdd(&g_sums[0], v0);
        atomicAdd(&g_sums[1], v1);
        atomicAdd(&g_sums[2], v2);
        atomicAdd(&g_sums[3], v3);
        __threadfence();
        unsigned int old = atomicAdd(&g_count, 1u);
        s_is_last = (old == (unsigned int)(nblocks - 1)) ? 1 : 0;
    }
    __syncthreads();

    if (s_is_last && tid == 0) {
        __threadfence();
        volatile float* gs = g_sums;
        float xywh  = gs[0];
        float obj   = gs[1];
        float noobj = gs[2];
        float cls   = gs[3];
        out[0] = (L_COORD * xywh + obj + L_NOOBJ * noobj + cls) * inv_bs;
        out[1] = xywh;
        out[2] = obj;
        out[3] = noobj;
        out[4] = cls;
        // reset for the next graph replay (deterministic)
        g_sums[0] = 0.0f; g_sums[1] = 0.0f;
        g_sums[2] = 0.0f; g_sums[3] = 0.0f;
        g_count = 0u;
        __threadfence();
    }
}

extern "C" void kernel_launch(void* const* d_in, const int* in_sizes, int n_in,
                              void* d_out, int out_size) {
    const float4* pred4 = (const float4*)d_in[0];
    const float4* tgt4  = (const float4*)d_in[1];
    int ncells = in_sizes[0] / N_CH;            // 8192*7*7 = 401408
    int bs = ncells / (S_GRID * S_GRID);        // 8192
    int total_v4 = in_sizes[0] / 4;             // ncells*30/4 (divisible: ncells even)
    int nblocks = (ncells + TPB - 1) / TPB;     // 3136

    yolo_loss_kernel<<<nblocks, TPB>>>(pred4, tgt4, (float*)d_out,
                                       ncells, 1.0f / (float)bs, nblocks, total_v4);
}

// round 3
// speedup vs baseline: 1.2150x; 1.1390x over previous
#include <cuda_runtime.h>
#include <cstdint>

#define S_GRID 7
#define N_CH 30
#define L_COORD 5.0f
#define L_NOOBJ 0.5f

#define TPB 128                    // threads per block = cells per block
#define FPB (TPB * N_CH)           // 3840 floats staged per tensor
#define V4PB (FPB / 4)             // 960 float4 per tensor (=7.5 per thread)

__device__ float g_sums[4];        // [0]=xy+wh [1]=obj [2]=noobj [3]=class
__device__ unsigned int g_count;

__device__ __forceinline__ void cp_async16(uint32_t smem_addr, const void* gptr) {
    asm volatile("cp.async.cg.shared.global [%0], [%1], 16;"
                 :: "r"(smem_addr), "l"(gptr) : "memory");
}

__global__ __launch_bounds__(TPB) void yolo_loss_kernel(
    const float4* __restrict__ pred4,
    const float4* __restrict__ tgt4,
    float* __restrict__ out,
    float inv_bs, int nblocks)
{
    __shared__ float sp[FPB];
    __shared__ float st[FPB];
    __shared__ float red[4][4];        // 4 warps
    __shared__ int   s_is_last;

    const int tid = threadIdx.x;
    const long v4base = (long)blockIdx.x * V4PB;

    // ---- coalesced staging via cp.async (no register round-trip, deep MLP) ----
    uint32_t sp_base = (uint32_t)__cvta_generic_to_shared(sp);
    uint32_t st_base = (uint32_t)__cvta_generic_to_shared(st);

    // 960 float4 per tensor, 128 threads: threads 0..63 do 8, 64..127 do 7
#pragma unroll
    for (int k = 0; k < 7; k++) {
        int idx = tid + k * TPB;
        cp_async16(sp_base + idx * 16, pred4 + v4base + idx);
        cp_async16(st_base + idx * 16, tgt4  + v4base + idx);
    }
    {
        int idx = tid + 7 * TPB;
        if (idx < V4PB) {
            cp_async16(sp_base + idx * 16, pred4 + v4base + idx);
            cp_async16(st_base + idx * 16, tgt4  + v4base + idx);
        }
    }
    asm volatile("cp.async.commit_group;" ::: "memory");
    asm volatile("cp.async.wait_group 0;" ::: "memory");
    __syncthreads();

    // ---- per-cell loss ----
    const float* p = sp + tid * N_CH;
    const float* t = st + tid * N_CH;

    float conf_t = t[4];
    float coord = (conf_t > 0.0f) ? 1.0f : 0.0f;
    float noobj = (conf_t == 0.0f) ? 1.0f : 0.0f;

    // target box xyxy (mirror reference op order)
    float tax = t[0] / (float)S_GRID;
    float tay = t[1] / (float)S_GRID;
    float thw = 0.5f * t[2];
    float thh = 0.5f * t[3];
    float tx1 = tax - thw, ty1 = tay - thh;
    float tx2 = tax + thw, ty2 = tay + thh;
    float area_t = (tx2 - tx1) * (ty2 - ty1);

    float iou[2];
#pragma unroll
    for (int b = 0; b < 2; b++) {
        const float* pb = p + 5 * b;
        float pax = pb[0] / (float)S_GRID;
        float pay = pb[1] / (float)S_GRID;
        float phw = 0.5f * pb[2];
        float phh = 0.5f * pb[3];
        float px1 = pax - phw, py1 = pay - phh;
        float px2 = pax + phw, py2 = pay + phh;

        float ltx = fmaxf(px1, tx1);
        float lty = fmaxf(py1, ty1);
        float rbx = fminf(px2, tx2);
        float rby = fminf(py2, ty2);
        float w = fmaxf(rbx - ltx, 0.0f);
        float h = fmaxf(rby - lty, 0.0f);
        float inter = w * h;
        float area_p = (px2 - px1) * (py2 - py1);
        iou[b] = inter / (area_p + area_t - inter);
    }

    // argmax first-occurrence tie-break: pick box1 only if strictly greater
    int best = (iou[1] > iou[0]) ? 1 : 0;
    float max_iou = fmaxf(iou[0], iou[1]);
    const float* resp = p + 5 * best;

    float dx = resp[0] - t[0];
    float dy = resp[1] - t[1];
    float loss_xy = dx * dx + dy * dy;

    float dw = sqrtf(resp[2]) - sqrtf(t[2]);
    float dh = sqrtf(resp[3]) - sqrtf(t[3]);
    float loss_wh = dw * dw + dh * dh;

    float dob = resp[4] - max_iou;
    float loss_obj = dob * dob;

    float loss_cls = 0.0f;
#pragma unroll
    for (int c = 10; c < 30; c++) {
        float d = p[c] - t[c];
        loss_cls += d * d;
    }

    float d4 = p[4] - t[4];
    float d9 = p[9] - t[9];
    float loss_no = d4 * d4 + d9 * d9;

    float s_xywh  = coord * (loss_xy + loss_wh);
    float s_obj   = coord * loss_obj;
    float s_noobj = noobj * loss_no;
    float s_cls   = coord * loss_cls;

    // ---- warp reduction ----
#pragma unroll
    for (int off = 16; off > 0; off >>= 1) {
        s_xywh  += __shfl_down_sync(0xFFFFFFFFu, s_xywh,  off);
        s_obj   += __shfl_down_sync(0xFFFFFFFFu, s_obj,   off);
        s_noobj += __shfl_down_sync(0xFFFFFFFFu, s_noobj, off);
        s_cls   += __shfl_down_sync(0xFFFFFFFFu, s_cls,   off);
    }

    int wid = tid >> 5;
    int lid = tid & 31;
    if (lid == 0) {
        red[0][wid] = s_xywh;
        red[1][wid] = s_obj;
        red[2][wid] = s_noobj;
        red[3][wid] = s_cls;
    }
    __syncthreads();

    // ---- block total + global accumulate + last-block finalize ----
    if (tid == 0) {
        float v0 = red[0][0] + red[0][1] + red[0][2] + red[0][3];
        float v1 = red[1][0] + red[1][1] + red[1][2] + red[1][3];
        float v2 = red[2][0] + red[2][1] + red[2][2] + red[2][3];
        float v3 = red[3][0] + red[3][1] + red[3][2] + red[3][3];
        atomicAdd(&g_sums[0], v0);
        atomicAdd(&g_sums[1], v1);
        atomicAdd(&g_sums[2], v2);
        atomicAdd(&g_sums[3], v3);
        __threadfence();
        unsigned int old = atomicAdd(&g_count, 1u);
        s_is_last = (old == (unsigned int)(nblocks - 1)) ? 1 : 0;
    }
    __syncthreads();

    if (s_is_last && tid == 0) {
        __threadfence();
        volatile float* gs = g_sums;
        float xywh  = gs[0];
        float obj   = gs[1];
        float noobj = gs[2];
        float cls   = gs[3];
        out[0] = (L_COORD * xywh + obj + L_NOOBJ * noobj + cls) * inv_bs;
        out[1] = xywh;
        out[2] = obj;
        out[3] = noobj;
        out[4] = cls;
        // reset for next graph replay (deterministic)
        g_sums[0] = 0.0f; g_sums[1] = 0.0f;
        g_sums[2] = 0.0f; g_sums[3] = 0.0f;
        g_count = 0u;
        __threadfence();
    }
}

extern "C" void kernel_launch(void* const* d_in, const int* in_sizes, int n_in,
                              void* d_out, int out_size) {
    const float4* pred4 = (const float4*)d_in[0];
    const float4* tgt4  = (const float4*)d_in[1];
    int ncells = in_sizes[0] / N_CH;            // 8192*7*7 = 401408 (= 3136*128)
    int bs = ncells / (S_GRID * S_GRID);        // 8192
    int nblocks = (ncells + TPB - 1) / TPB;     // 3136, exact

    yolo_loss_kernel<<<nblocks, TPB>>>(pred4, tgt4, (float*)d_out,
                                       1.0f / (float)bs, nblocks);
}

// round 4
// speedup vs baseline: 1.3282x; 1.0932x over previous
#include <cuda_runtime.h>
#include <cstdint>

#define S_GRID 7
#define N_CH 30
#define L_COORD 5.0f
#define L_NOOBJ 0.5f

#define TPB 128                     // threads per block = cells per tile
#define TILE_F (TPB * N_CH)         // 3840 floats per tensor per tile
#define TILE_V4 (TILE_F / 4)        // 960 float4 per tensor per tile
#define TILE_BYTES (TILE_F * 4)     // 15360 B per tensor per tile
#define GRID_BLOCKS 444             // 148 SMs * 3 resident blocks

__device__ float g_sums[4];         // [0]=xy+wh [1]=obj [2]=noobj [3]=class
__device__ unsigned int g_count;

__device__ __forceinline__ void cp_async16(uint32_t smem_addr, const void* gptr) {
    asm volatile("cp.async.cg.shared.global [%0], [%1], 16;"
                 :: "r"(smem_addr), "l"(gptr) : "memory");
}

__device__ __forceinline__ void load_tile(
    uint32_t sp_base, uint32_t st_base,
    const float4* __restrict__ pred4, const float4* __restrict__ tgt4,
    int tile, int tid, long total_v4)
{
    long v4base = (long)tile * TILE_V4;
#pragma unroll
    for (int k = 0; k < 7; k++) {
        int idx = tid + k * TPB;
        long g = v4base + idx;
        if (g < total_v4) {
            cp_async16(sp_base + idx * 16, pred4 + g);
            cp_async16(st_base + idx * 16, tgt4  + g);
        }
    }
    int idx = tid + 7 * TPB;
    if (idx < TILE_V4) {
        long g = v4base + idx;
        if (g < total_v4) {
            cp_async16(sp_base + idx * 16, pred4 + g);
            cp_async16(st_base + idx * 16, tgt4  + g);
        }
    }
}

extern __shared__ float smem_dyn[];  // [2 tensors][2 stages][TILE_F]

__global__ __launch_bounds__(TPB) void yolo_loss_kernel(
    const float4* __restrict__ pred4,
    const float4* __restrict__ tgt4,
    float* __restrict__ out,
    float inv_bs, int ntiles, int ncells, long total_v4, int nblocks)
{
    __shared__ float red[4][4];
    __shared__ int   s_is_last;

    float* sp[2] = { smem_dyn,              smem_dyn + TILE_F     };
    float* st[2] = { smem_dyn + 2 * TILE_F, smem_dyn + 3 * TILE_F };

    const int tid = threadIdx.x;
    const int bid = blockIdx.x;

    uint32_t spb[2] = { (uint32_t)__cvta_generic_to_shared(sp[0]),
                        (uint32_t)__cvta_generic_to_shared(sp[1]) };
    uint32_t stb[2] = { (uint32_t)__cvta_generic_to_shared(st[0]),
                        (uint32_t)__cvta_generic_to_shared(st[1]) };

    float a_xywh = 0.0f, a_obj = 0.0f, a_noobj = 0.0f, a_cls = 0.0f;

    int tile = bid;
    int stage = 0;
    if (tile < ntiles) {
        load_tile(spb[0], stb[0], pred4, tgt4, tile, tid, total_v4);
        asm volatile("cp.async.commit_group;" ::: "memory");
    }

    while (tile < ntiles) {
        int next = tile + nblocks;
        if (next < ntiles) {
            load_tile(spb[stage ^ 1], stb[stage ^ 1], pred4, tgt4, next, tid, total_v4);
            asm volatile("cp.async.commit_group;" ::: "memory");
            asm volatile("cp.async.wait_group 1;" ::: "memory");
        } else {
            asm volatile("cp.async.wait_group 0;" ::: "memory");
        }
        __syncthreads();

        // ---- per-cell loss from smem ----
        int cell = tile * TPB + tid;
        if (cell < ncells) {
            const float* p = sp[stage] + tid * N_CH;
            const float* t = st[stage] + tid * N_CH;

            float conf_t = t[4];
            float coord = (conf_t > 0.0f) ? 1.0f : 0.0f;
            float noobj = (conf_t == 0.0f) ? 1.0f : 0.0f;

            float tax = t[0] / (float)S_GRID;
            float tay = t[1] / (float)S_GRID;
            float thw = 0.5f * t[2];
            float thh = 0.5f * t[3];
            float tx1 = tax - thw, ty1 = tay - thh;
            float tx2 = tax + thw, ty2 = tay + thh;
            float area_t = (tx2 - tx1) * (ty2 - ty1);

            float iou[2];
#pragma unroll
            for (int b = 0; b < 2; b++) {
                const float* pb = p + 5 * b;
                float pax = pb[0] / (float)S_GRID;
                float pay = pb[1] / (float)S_GRID;
                float phw = 0.5f * pb[2];
                float phh = 0.5f * pb[3];
                float px1 = pax - phw, py1 = pay - phh;
                float px2 = pax + phw, py2 = pay + phh;

                float ltx = fmaxf(px1, tx1);
                float lty = fmaxf(py1, ty1);
                float rbx = fminf(px2, tx2);
                float rby = fminf(py2, ty2);
                float w = fmaxf(rbx - ltx, 0.0f);
                float h = fmaxf(rby - lty, 0.0f);
                float inter = w * h;
                float area_p = (px2 - px1) * (py2 - py1);
                iou[b] = inter / (area_p + area_t - inter);
            }

            int best = (iou[1] > iou[0]) ? 1 : 0;
            float max_iou = fmaxf(iou[0], iou[1]);
            const float* resp = p + 5 * best;

            float dx = resp[0] - t[0];
            float dy = resp[1] - t[1];
            float loss_xy = dx * dx + dy * dy;

            float dw = sqrtf(resp[2]) - sqrtf(t[2]);
            float dh = sqrtf(resp[3]) - sqrtf(t[3]);
            float loss_wh = dw * dw + dh * dh;

            float dob = resp[4] - max_iou;
            float loss_obj = dob * dob;

            float loss_cls = 0.0f;
#pragma unroll
            for (int c = 10; c < 30; c++) {
                float d = p[c] - t[c];
                loss_cls += d * d;
            }

            float d4 = p[4] - t[4];
            float d9 = p[9] - t[9];
            float loss_no = d4 * d4 + d9 * d9;

            a_xywh  += coord * (loss_xy + loss_wh);
            a_obj   += coord * loss_obj;
            a_noobj += noobj * loss_no;
            a_cls   += coord * loss_cls;
        }
        __syncthreads();   // compute done before this buffer is refilled
        stage ^= 1;
        tile = next;
    }

    // ---- one reduction per block ----
#pragma unroll
    for (int off = 16; off > 0; off >>= 1) {
        a_xywh  += __shfl_down_sync(0xFFFFFFFFu, a_xywh,  off);
        a_obj   += __shfl_down_sync(0xFFFFFFFFu, a_obj,   off);
        a_noobj += __shfl_down_sync(0xFFFFFFFFu, a_noobj, off);
        a_cls   += __shfl_down_sync(0xFFFFFFFFu, a_cls,   off);
    }

    int wid = tid >> 5;
    int lid = tid & 31;
    if (lid == 0) {
        red[0][wid] = a_xywh;
        red[1][wid] = a_obj;
        red[2][wid] = a_noobj;
        red[3][wid] = a_cls;
    }
    __syncthreads();

    if (tid == 0) {
        float v0 = red[0][0] + red[0][1] + red[0][2] + red[0][3];
        float v1 = red[1][0] + red[1][1] + red[1][2] + red[1][3];
        float v2 = red[2][0] + red[2][1] + red[2][2] + red[2][3];
        float v3 = red[3][0] + red[3][1] + red[3][2] + red[3][3];
        atomicAdd(&g_sums[0], v0);
        atomicAdd(&g_sums[1], v1);
        atomicAdd(&g_sums[2], v2);
        atomicAdd(&g_sums[3], v3);
        __threadfence();
        unsigned int old = atomicAdd(&g_count, 1u);
        s_is_last = (old == (unsigned int)(nblocks - 1)) ? 1 : 0;
    }
    __syncthreads();

    if (s_is_last && tid == 0) {
        __threadfence();
        volatile float* gs = g_sums;
        float xywh  = gs[0];
        float obj   = gs[1];
        float noobj = gs[2];
        float cls   = gs[3];
        out[0] = (L_COORD * xywh + obj + L_NOOBJ * noobj + cls) * inv_bs;
        out[1] = xywh;
        out[2] = obj;
        out[3] = noobj;
        out[4] = cls;
        g_sums[0] = 0.0f; g_sums[1] = 0.0f;
        g_sums[2] = 0.0f; g_sums[3] = 0.0f;
        g_count = 0u;
        __threadfence();
    }
}

extern "C" void kernel_launch(void* const* d_in, const int* in_sizes, int n_in,
                              void* d_out, int out_size) {
    const float4* pred4 = (const float4*)d_in[0];
    const float4* tgt4  = (const float4*)d_in[1];
    int ncells = in_sizes[0] / N_CH;                 // 401408
    int bs = ncells / (S_GRID * S_GRID);             // 8192
    long total_v4 = (long)in_sizes[0] / 4;
    int ntiles = (ncells + TPB - 1) / TPB;           // 3136
    int nblocks = GRID_BLOCKS < ntiles ? GRID_BLOCKS : ntiles;

    size_t smem_bytes = 4 * (size_t)TILE_F * sizeof(float);  // 61440
    static int attr_set = 0;
    if (!attr_set) {
        cudaFuncSetAttribute(yolo_loss_kernel,
                             cudaFuncAttributeMaxDynamicSharedMemorySize,
                             (int)smem_bytes);
        attr_set = 1;
    }

    yolo_loss_kernel<<<nblocks, TPB, smem_bytes>>>(
        pred4, tgt4, (float*)d_out,
        1.0f / (float)bs, ntiles, ncells, total_v4, nblocks);
}